// round 13
// baseline (speedup 1.0000x reference)
#include <cuda_runtime.h>
#include <cstdint>

// ----------------------------------------------------------------------------
// BlockSparseLinear: y[8192,4096] = x[8192,4096] @ W^T + bias
// W block-sparse: 64 row-blocks x 16 nonzero 64x64 col-blocks each.
//
// R12: crossbar-byte reduction. Warp tile 32x64 -> 64x64 (mt=4): fragment
// bytes/MMA 192 -> 128, smem crossbar demand drops below the 128 B/cyc/SM cap
// (was ~148). CTA: 256 tokens x 64 outs, 4 warps, 128 accum regs/thread,
// 2 CTAs/SM. Pipeline = R10: 2-stage cp.async ring, one barrier per chunk,
// ldmatrix.x4 fragments, W pre-converted to tf32 bits, A cvt.rna on regs
// (arithmetic unchanged -> rel_err must stay 2.935e-4).
// ----------------------------------------------------------------------------

static constexpr int IN_F  = 4096;
static constexpr int OUT_F = 4096;
static constexpr int BLKSZ = 64;
static constexpr int KBLK  = 16;
static constexpr int BM    = 256;          // tokens per CTA
static constexpr int KC    = 32;           // K per chunk (half a col-block)
static constexpr int NCHUNK = KBLK * 2;    // 32
static constexpr int NSTAGE = 2;
static constexpr int NTHREADS = 128;       // 4 warps x 64 rows each

static constexpr int A_BUF = BM * KC;          // 8192 floats
static constexpr int B_BUF = BLKSZ * KC;       // 2048 floats
static constexpr int STAGE_FLOATS = A_BUF + B_BUF;              // 10240
static constexpr int DYN_SMEM = NSTAGE * STAGE_FLOATS * 4;      // 81920 B

// Pre-converted W (tf32 bits), same layout as w: [1024][64][64].
static constexpr int W_ELEMS = 1024 * 64 * 64;
__device__ uint32_t g_wtf[W_ELEMS];

static __device__ __forceinline__ uint32_t f2tf(float f) {
    uint32_t u;
    asm("cvt.rna.tf32.f32 %0, %1;" : "=r"(u) : "f"(f));
    return u;
}

static __device__ __forceinline__ void cp16(uint32_t dst_smem, const void* src) {
    asm volatile("cp.async.cg.shared.global [%0], [%1], 16;"
                 :: "r"(dst_smem), "l"(src) : "memory");
}
static __device__ __forceinline__ void cp_commit() {
    asm volatile("cp.async.commit_group;" ::: "memory");
}
template <int N>
static __device__ __forceinline__ void cp_wait() {
    asm volatile("cp.async.wait_group %0;" :: "n"(N) : "memory");
}

static __device__ __forceinline__ void ldsm4(uint32_t& r0, uint32_t& r1,
                                             uint32_t& r2, uint32_t& r3,
                                             uint32_t addr) {
    asm volatile("ldmatrix.sync.aligned.m8n8.x4.shared.b16 {%0,%1,%2,%3}, [%4];"
                 : "=r"(r0), "=r"(r1), "=r"(r2), "=r"(r3) : "r"(addr));
}

static __device__ __forceinline__ void mma_tf32_16x8x8(
    float& d0, float& d1, float& d2, float& d3,
    uint32_t a0, uint32_t a1, uint32_t a2, uint32_t a3,
    uint32_t b0, uint32_t b1)
{
    asm volatile(
        "mma.sync.aligned.m16n8k8.row.col.f32.tf32.tf32.f32 "
        "{%0,%1,%2,%3}, {%4,%5,%6,%7}, {%8,%9}, {%0,%1,%2,%3};"
        : "+f"(d0), "+f"(d1), "+f"(d2), "+f"(d3)
        : "r"(a0), "r"(a1), "r"(a2), "r"(a3), "r"(b0), "r"(b1));
}

// row-major [rows][KC] with float4-granule swizzle: granule q of row r lands
// at float offset r*KC + ((q ^ (r & 7)) << 2). Conflict-free for cp.async
// stores AND for ldmatrix (8-row reads hit positions q^0..q^7, all distinct).
static __device__ __forceinline__ uint32_t swz_off(int row, int q) {
    return (uint32_t)(row * KC + (((q ^ (row & 7)) << 2))) * 4u;
}

// ---- pre-pass: W fp32 -> tf32 bits (16MB, ~7us) ----------------------------
__global__ __launch_bounds__(256)
void convert_w_kernel(const float* __restrict__ w)
{
    const int i = blockIdx.x * 256 + threadIdx.x;   // float4 index
    const float4* src = reinterpret_cast<const float4*>(w);
    uint4* dst = reinterpret_cast<uint4*>(g_wtf);
    float4 v = src[i];
    uint4 t;
    t.x = f2tf(v.x); t.y = f2tf(v.y); t.z = f2tf(v.z); t.w = f2tf(v.w);
    dst[i] = t;
}

// ----------------------------------------------------------------------------
__global__ __launch_bounds__(NTHREADS, 2)
void bsl_wide_kernel(const float* __restrict__ x,
                     const float* __restrict__ bias,
                     const int*   __restrict__ col_idx,
                     float*       __restrict__ out)
{
    extern __shared__ float smem[];

    const int tid  = threadIdx.x;
    const int wid  = tid >> 5;
    const int lane = tid & 31;
    const int g    = lane >> 2;          // 0..7
    const int cq   = lane & 3;           // 0..3

    const int rb   = blockIdx.x;
    const int tok0 = blockIdx.y * BM;
    const int warp_m = wid * 64;         // 64 rows per warp

    int colreg[KBLK];
    #pragma unroll
    for (int i = 0; i < KBLK; ++i) colreg[i] = __ldg(col_idx + rb * KBLK + i);

    const uint32_t smem_u = (uint32_t)__cvta_generic_to_shared(smem);

    const int srow = tid >> 3;           // staging: 16 rows per pass
    const int sq   = tid & 7;            // float4 granule within row

    // ldmatrix per-lane geometry: tile index tl = lane>>3 (0..3)
    const int tl       = lane >> 3;
    const int tl_row   = ((tl & 1) << 3) + (lane & 7);  // +row within 16-row pair
    const int tl_q     = tl >> 1;                       // +granule (0 or 1)

    float acc[4][8][4];                  // 128 accumulators
    #pragma unroll
    for (int mt = 0; mt < 4; ++mt)
        #pragma unroll
        for (int nt = 0; nt < 8; ++nt)
            #pragma unroll
            for (int r = 0; r < 4; ++r) acc[mt][nt][r] = 0.0f;

    auto stage = [&](int kc) {
        const int s  = kc % NSTAGE;
        const int cb = kc >> 1;
        const int h  = kc & 1;
        const int c  = colreg[cb];
        const uint32_t Ab = smem_u + (uint32_t)(s * STAGE_FLOATS) * 4u;
        const uint32_t Bb = Ab + (uint32_t)A_BUF * 4u;

        const float* xsrc = x + (size_t)tok0 * IN_F + (size_t)c * BLKSZ + h * KC;
        #pragma unroll
        for (int i = 0; i < 16; ++i) {           // 256 rows, 16 per pass
            const int row = srow + i * 16;
            cp16(Ab + swz_off(row, sq), xsrc + (size_t)row * IN_F + sq * 4);
        }
        const uint32_t* wsrc = g_wtf + ((size_t)rb * KBLK + cb) * (BLKSZ * BLKSZ) + h * KC;
        #pragma unroll
        for (int i = 0; i < 4; ++i) {            // 64 rows
            const int row = srow + i * 16;
            cp16(Bb + swz_off(row, sq), wsrc + (size_t)row * BLKSZ + sq * 4);
        }
        cp_commit();
    };

    stage(0);

    for (int kc = 0; kc < NCHUNK; ++kc) {
        cp_wait<0>();      // chunk kc landed (only group pending here)
        __syncthreads();   // publish chunk kc; proves compute(kc-1) done by all
                           // -> slot (kc+1)%2 == (kc-1)%2 is free to restage

        if (kc + 1 < NCHUNK) stage(kc + 1);

        const int s = kc % NSTAGE;
        const uint32_t Abase = smem_u + (uint32_t)(s * STAGE_FLOATS) * 4u;
        const uint32_t Bbase = Abase + (uint32_t)A_BUF * 4u;

        #pragma unroll
        for (int k0 = 0; k0 < KC; k0 += 8) {
            const int qb = (k0 >> 2) + tl_q;     // this lane's granule

            // B fragments: 4 x ldmatrix.x4 (pre-converted tf32 bits)
            uint32_t b[8][2];
            #pragma unroll
            for (int j = 0; j < 4; ++j) {
                const int row = j * 16 + tl_row;
                ldsm4(b[2*j][0], b[2*j+1][0], b[2*j][1], b[2*j+1][1],
                      Bbase + swz_off(row, qb));
            }
            // A fragments: 4 x ldmatrix.x4 (raw x bits) + cvt.rna on regs
            uint32_t a[4][4];
            #pragma unroll
            for (int mt = 0; mt < 4; ++mt) {
                const int row = warp_m + mt * 16 + tl_row;
                ldsm4(a[mt][0], a[mt][1], a[mt][2], a[mt][3],
                      Abase + swz_off(row, qb));
                #pragma unroll
                for (int r = 0; r < 4; ++r)
                    a[mt][r] = f2tf(__uint_as_float(a[mt][r]));
            }
            #pragma unroll
            for (int mt = 0; mt < 4; ++mt)
                #pragma unroll
                for (int nt = 0; nt < 8; ++nt)
                    mma_tf32_16x8x8(acc[mt][nt][0], acc[mt][nt][1],
                                    acc[mt][nt][2], acc[mt][nt][3],
                                    a[mt][0], a[mt][1], a[mt][2], a[mt][3],
                                    b[nt][0], b[nt][1]);
        }
    }

    // ---- epilogue: +bias, store fp32 ----
    const float* bsrc = bias + rb * BLKSZ;
    #pragma unroll
    for (int mt = 0; mt < 4; ++mt) {
        const int row0 = tok0 + warp_m + mt * 16 + g;
        #pragma unroll
        for (int nt = 0; nt < 8; ++nt) {
            const int col = nt * 8 + 2 * cq;
            const float2 bv = *reinterpret_cast<const float2*>(bsrc + col);
            float* d0 = out + (size_t)row0 * OUT_F + rb * BLKSZ + col;
            float* d1 = out + (size_t)(row0 + 8) * OUT_F + rb * BLKSZ + col;
            float2 o0, o1;
            o0.x = acc[mt][nt][0] + bv.x;
            o0.y = acc[mt][nt][1] + bv.y;
            o1.x = acc[mt][nt][2] + bv.x;
            o1.y = acc[mt][nt][3] + bv.y;
            *reinterpret_cast<float2*>(d0) = o0;
            *reinterpret_cast<float2*>(d1) = o1;
        }
    }
}

// ----------------------------------------------------------------------------
extern "C" void kernel_launch(void* const* d_in, const int* in_sizes, int n_in,
                              void* d_out, int out_size)
{
    const float* x = nullptr;
    const float* w = nullptr;
    const float* bias = nullptr;
    const int* row_idx = nullptr;
    const int* col_idx = nullptr;

    for (int i = 0; i < n_in; ++i) {
        long s = (long)in_sizes[i];
        if (s == 8192L * 4096L)          x = (const float*)d_in[i];
        else if (s == 1024L * 64L * 64L) w = (const float*)d_in[i];
        else if (s == 4096L)             bias = (const float*)d_in[i];
        else if (s == 1024L) {
            if (!row_idx) row_idx = (const int*)d_in[i];
            else          col_idx = (const int*)d_in[i];
        }
    }
    if (!x || !w || !bias || !col_idx) {   // positional fallback
        x       = (const float*)d_in[0];
        w       = (const float*)d_in[1];
        bias    = (const float*)d_in[2];
        row_idx = (const int*)d_in[3];
        col_idx = (const int*)d_in[4];
    }
    (void)row_idx; (void)out_size;

    // Pass 1: W -> tf32 bits (1048576 float4s).
    convert_w_kernel<<<W_ELEMS / 4 / 256, 256>>>(w);

    // Pass 2: main GEMM.
    cudaFuncSetAttribute(bsl_wide_kernel,
                         cudaFuncAttributeMaxDynamicSharedMemorySize, DYN_SMEM);
    dim3 grid(64, 32);   // x = row-block (fast, shares x via L2), y = token tile
    bsl_wide_kernel<<<grid, NTHREADS, DYN_SMEM>>>(x, bias, col_idx, (float*)d_out);
}